// round 13
// baseline (speedup 1.0000x reference)
#include <cuda_runtime.h>
#include <math_constants.h>

// Problem shape (fixed by the reference): B=32768 rows, C=1000 cols.
#define B_ROWS 32768
#define C_COLS 1000
#define C_VEC  250          // float4s per row; row stride 4000 B (16B-aligned)
#define WARPS_PER_BLK 8
#define NBLOCKS 592         // 148 SMs x 4 resident CTAs -> single persistent wave
#define TOTAL_WARPS (NBLOCKS * WARPS_PER_BLK)   // 4736

#define STATIC_PER_WARP 6
#define STATIC_ROWS (TOTAL_WARPS * STATIC_PER_WARP)   // 28416; tail = 4352 stolen

// Scratch (no device allocation allowed).
__device__ float g_block_sum[NBLOCKS];
__device__ unsigned int g_ticket  = 0;            // re-armed each run
__device__ unsigned int g_row_ctr = STATIC_ROWS;  // steal counter; re-armed each run

// loss_row = sum_j softplus(x_j) - (any(label & x>0) ? sum_{label & x>0} x_j
//                                                     : max_{label} x_j)
// (gain_j == x_j and base == sum softplus(x_j) to ~1e-10 since |x| < ~6.)
// Branchless body, ONE MUFU per element: softplus(x)=max(x,0)+ln(1+e^{-|x|}),
// ln(1+u) by deg-5 minimax (A&S 4.1.44, |err|<=1e-5 abs on u in [0,1]).
__device__ __forceinline__ void process_row(
    const float* __restrict__ logits, const float* __restrict__ labels,
    unsigned row, int lane, float& base_acc, float& gain_acc)
{
    const float4* __restrict__ xr =
        reinterpret_cast<const float4*>(logits + (size_t)row * C_COLS);
    const float4* __restrict__ mr =
        reinterpret_cast<const float4*>(labels + (size_t)row * C_COLS);

    float pos  = 0.0f;          // sum of positive gains over true labels
    float tmax = -CUDART_INF_F; // max gain over true labels

    // 250 float4s over 32 lanes, fully unrolled so ptxas front-batches LDGs.
    #pragma unroll
    for (int i = 0; i < 8; ++i) {
        const int k = lane + i * 32;
        if (k < C_VEC) {
            const float4 x4 = __ldg(&xr[k]);
            const float4 m4 = __ldg(&mr[k]);
            const float xs[4] = {x4.x, x4.y, x4.z, x4.w};
            const float ms[4] = {m4.x, m4.y, m4.z, m4.w};
            #pragma unroll
            for (int j = 0; j < 4; ++j) {
                const float x  = xs[j];
                const float m  = ms[j];               // exactly 0.0f or 1.0f
                const float xp = fmaxf(x, 0.0f);
                const float u  = __expf(-fabsf(x));   // in (0, 1]
                float p = fmaf(0.03215845f, u, -0.13606275f);
                p = fmaf(p, u, 0.28947478f);
                p = fmaf(p, u, -0.49190896f);
                p = fmaf(p, u, 0.99949556f);
                base_acc += fmaf(p, u, xp);
                pos  = fmaf(m, xp, pos);              // adds x iff m & x>0
                tmax = fmaxf(tmax, fmaf(m - 1.0f, 1e30f, x));
            }
        }
    }

    // anyp == (warp-sum of pos) > 0 (pos is a sum of positives).
    if (__any_sync(0xFFFFFFFFu, pos > 0.0f)) {
        #pragma unroll
        for (int off = 16; off > 0; off >>= 1)
            pos += __shfl_xor_sync(0xFFFFFFFFu, pos, off);
        if (lane == 0) gain_acc += pos;
    } else {
        // All gains on true labels negative (rare; kept for full correctness).
        #pragma unroll
        for (int off = 16; off > 0; off >>= 1)
            tmax = fmaxf(tmax, __shfl_xor_sync(0xFFFFFFFFu, tmax, off));
        if (lane == 0) gain_acc += tmax;
    }
}

// Persistent kernel: 6 static rows per warp (87% of work, fully overlapped
// static addressing), then a work-stolen tail (13%) that absorbs the ~10%
// between-SM L2-die speed skew. Steal is pipelined one-ahead so the ATOMG
// round trip hides under row processing.
__global__ void __launch_bounds__(256, 4)
fused_loss_kernel(const float* __restrict__ logits,
                  const float* __restrict__ labels,
                  float* __restrict__ d_out)
{
    const int warp  = threadIdx.x >> 5;
    const int lane  = threadIdx.x & 31;
    const int gwarp = blockIdx.x * WARPS_PER_BLK + warp;

    float base_acc = 0.0f;   // per-lane sum of softplus over all my rows
    float gain_acc = 0.0f;   // lane 0: sum of per-row max_gain over my rows

    // Phase 1: static rows (compile-time strided addresses).
    #pragma unroll
    for (int k = 0; k < STATIC_PER_WARP; ++k)
        process_row(logits, labels, gwarp + k * TOTAL_WARPS,
                    lane, base_acc, gain_acc);

    // Phase 2: stolen tail, one-ahead pipelined.
    unsigned next;
    if (lane == 0) next = atomicAdd(&g_row_ctr, 1u);
    next = __shfl_sync(0xFFFFFFFFu, next, 0);
    while (next < B_ROWS) {
        const unsigned row = next;
        if (lane == 0) next = atomicAdd(&g_row_ctr, 1u);  // hide under body
        process_row(logits, labels, row, lane, base_acc, gain_acc);
        next = __shfl_sync(0xFFFFFFFFu, next, 0);
    }

    // Fold base across the warp once, at the very end.
    #pragma unroll
    for (int off = 16; off > 0; off >>= 1)
        base_acc += __shfl_xor_sync(0xFFFFFFFFu, base_acc, off);

    // Block-level fold of the 8 warp partials (base - gain).
    __shared__ float s_warp[WARPS_PER_BLK];
    __shared__ bool  s_last;
    if (lane == 0) s_warp[warp] = base_acc - gain_acc;
    __syncthreads();

    if (threadIdx.x == 0) {
        float acc = 0.0f;
        #pragma unroll
        for (int w = 0; w < WARPS_PER_BLK; ++w) acc += s_warp[w];
        g_block_sum[blockIdx.x] = acc;
        __threadfence();                       // publish partial before ticket
        const unsigned t = atomicAdd(&g_ticket, 1u);
        s_last = (t == (unsigned)(NBLOCKS - 1));
    }
    __syncthreads();

    // Last-arriving block: fixed-order reduction of the 592 partials.
    if (s_last) {
        __shared__ float s[256];
        float acc = 0.0f;
        for (int i = threadIdx.x; i < NBLOCKS; i += 256)
            acc += g_block_sum[i];
        s[threadIdx.x] = acc;
        __syncthreads();
        #pragma unroll
        for (int off = 128; off > 0; off >>= 1) {
            if (threadIdx.x < off) s[threadIdx.x] += s[threadIdx.x + off];
            __syncthreads();
        }
        if (threadIdx.x == 0) {
            d_out[0] = s[0] * (1.0f / (float)B_ROWS);
            g_ticket  = 0;                     // re-arm for graph replay
            g_row_ctr = STATIC_ROWS;
        }
    }
}

extern "C" void kernel_launch(void* const* d_in, const int* in_sizes, int n_in,
                              void* d_out, int out_size)
{
    const float* logits = (const float*)d_in[0];  // "output" [32768,1000] f32
    const float* labels = (const float*)d_in[1];  // "multilabels" [32768,1000] f32
    fused_loss_kernel<<<NBLOCKS, 256>>>(logits, labels, (float*)d_out);
}